// round 17
// baseline (speedup 1.0000x reference)
#include <cuda_runtime.h>
#include <cuda_fp16.h>
#include <cstdint>

// ---------------- problem constants ----------------
#define NN    50000
#define NNP   50048         // padded to multiple of 64 (GEMM M-tiles)
#define EE    800000
#define ET    (EE + NN)     // edges + self loops
#define GG    64
#define FIN   128
#define HID   32
#define HEADS 4
#define F1    (HEADS * HID) // 128
#define OUTD  10
#define NEG   0.2f
#define FULL  0xffffffffu
#define NB    196           // scan blocks: 196*256 = 50176 >= NN

// ---------------- device scratch (no allocations; zero-init at load) -----
__device__ __half g_w1t[F1 * FIN];      // W1^T: [n][k]
__device__ __half g_w2t[HID * F1];      // W2^T: [n][k]
__device__ __half g_h1h[NNP * F1];      // layer-1 features (fp16)
__device__ float  g_as1 [NN * HEADS];
__device__ float  g_ad1 [NN * HEADS];
__device__ __half g_x2h [NNP * F1];     // relu(agg1+b1) fp16 (padded rows zero)
__device__ __half g_h2h [NNP * HID];    // layer-2 features (fp16)
__device__ float  g_as2 [NN];
__device__ float  g_ad2 [NN];
__device__ float  g_psum[GG * HID];     // zero at load; re-zeroed in k8_fc
__device__ float  g_cnt [GG];
// CSR-by-destination
__device__ int    g_deg   [NN];         // zero at load; re-zeroed in k_scatter
__device__ int    g_cursor[NN];
__device__ int    g_rs    [NN + 1];
__device__ int    g_es    [ET];
// decoupled-lookback scan state
__device__ unsigned long long g_stat[NB];   // re-zeroed in k_scatter
__device__ int    g_tilectr;

__device__ __forceinline__ float lrelu(float v) { return v > 0.f ? v : NEG * v; }

// mma asm emitted ONLY via macro on named body-local scalars (probe-proven:
// no function boundary around accumulators -> registers, no lmem).
#define MMA16816(C0,C1,C2,C3,A0,A1,A2,A3,B0,B1)                               \
    asm volatile(                                                             \
        "mma.sync.aligned.m16n8k16.row.col.f32.f16.f16.f32 "                  \
        "{%0,%1,%2,%3}, {%4,%5,%6,%7}, {%8,%9}, {%0,%1,%2,%3};\n"             \
        : "+f"(C0), "+f"(C1), "+f"(C2), "+f"(C3)                              \
        : "r"(A0), "r"(A1), "r"(A2), "r"(A3), "r"(B0), "r"(B1))

// ---------------- K0b: count in-degree (deg starts zeroed) ---------------
__global__ void k_count(const int* __restrict__ dst) {
    const int e = blockIdx.x * blockDim.x + threadIdx.x;
    if (e < EE) atomicAdd(&g_deg[dst[e]], 1);
}

// ---------------- scan: single-kernel decoupled lookback -----------------
__global__ void k_scan() {
    __shared__ int sbid;
    __shared__ int ws[8];
    __shared__ int s_prefix;
    const int tid = threadIdx.x, lane = tid & 31, wid = tid >> 5;
    if (tid == 0) sbid = atomicAdd(&g_tilectr, 1);
    __syncthreads();
    const int bid = sbid;
    const int i   = bid * 256 + tid;
    const int v   = (i < NN) ? (g_deg[i] + 1) : 0;   // +1 = self loop

    int s = v;
    #pragma unroll
    for (int o = 1; o < 32; o <<= 1) {
        const int t = __shfl_up_sync(FULL, s, o);
        if (lane >= o) s += t;
    }
    if (lane == 31) ws[wid] = s;
    __syncthreads();
    if (wid == 0) {
        int t = (lane < 8) ? ws[lane] : 0;
        #pragma unroll
        for (int o = 1; o < 8; o <<= 1) {
            const int u = __shfl_up_sync(FULL, t, o);
            if (lane >= o) t += u;
        }
        if (lane < 8) ws[lane] = t;
    }
    __syncthreads();
    const int incl  = (wid ? ws[wid - 1] : 0) + s;
    const int total = ws[7];

    if (tid == 0) {
        if (bid > 0)
            atomicExch(&g_stat[bid], (1ull << 32) | (unsigned int)total);
        int prefix = 0;
        if (bid > 0) {
            int k = bid - 1;
            while (true) {
                unsigned long long st;
                do { st = *(volatile unsigned long long*)&g_stat[k]; }
                while ((st >> 32) == 0ull);
                prefix += (int)(unsigned int)(st & 0xffffffffull);
                if ((st >> 32) == 2ull) break;
                k--;
            }
        }
        s_prefix = prefix;
        atomicExch(&g_stat[bid], (2ull << 32) | (unsigned int)(prefix + total));
    }
    __syncthreads();
    const int base = s_prefix;
    if (i < NN) {
        g_rs[i + 1] = base + incl;
        g_cursor[i] = base + incl - v;
    }
    if (i == 0) g_rs[0] = 0;
}

// ---------------- K_SCAT: CSR permutation + scan-state cleanup -----------
// Runs after k_scan on the same stream: g_deg/g_stat/g_tilectr are dead,
// re-zero them here for the next graph replay (removes k_cleanup launch).
__global__ void k_scatter(const int* __restrict__ src, const int* __restrict__ dst) {
    const int t  = blockIdx.x * blockDim.x + threadIdx.x;
    if (t < NN) g_deg[t] = 0;
    if (t < NB) g_stat[t] = 0ull;
    if (t == 0) g_tilectr = 0;
    const int e0 = t * 2;
    if (e0 >= ET) return;
    int si0, di0, si1, di1;
    if (e0 < EE) {              // EE even: pair never straddles boundary
        si0 = src[e0];     di0 = dst[e0];
        si1 = src[e0 + 1]; di1 = dst[e0 + 1];
    } else {
        si0 = di0 = e0 - EE;
        si1 = di1 = e0 + 1 - EE;
    }
    const int p0 = atomicAdd(&g_cursor[di0], 1);
    const int p1 = atomicAdd(&g_cursor[di1], 1);
    g_es[p0] = si0;
    g_es[p1] = si1;
}

// ---------------- weight conversion ----------------
__global__ void k_cvtw(const float* __restrict__ W1, const float* __restrict__ W2) {
    const int t = blockIdx.x * blockDim.x + threadIdx.x;   // 64*256 = 16384
    if (t < F1 * FIN) {
        const int n = t >> 7, k = t & 127;
        g_w1t[t] = __float2half(W1[k * F1 + n]);
    }
    if (t < HID * F1) {
        const int n = t >> 7, k = t & 127;
        g_w2t[t] = __float2half(W2[k * HID + n]);
    }
}

// ---------------- TC GEMM 1 (+fused x->fp16 conversion, +fused att dots) --
__global__ __launch_bounds__(512) void k_gemm1_tc(
        const float* __restrict__ x,
        const float* __restrict__ as1, const float* __restrict__ ad1) {
    __shared__ __half as[64][136];
    const int m0  = blockIdx.x * 64;
    const int tid = threadIdx.x, lane = tid & 31, w = tid >> 5;
    const int wr  = w & 3, wc = w >> 2;

    // load A tile 64x128 floats -> fp16 smem: 2048 float4, 512 threads x 4
    {
        const float4* x4 = (const float4*)x;
        #pragma unroll
        for (int it = 0; it < 4; it++) {
            const int u  = it * 512 + tid;
            const int r  = u >> 5, c4 = u & 31;
            const int gr = m0 + r;
            float4 f = make_float4(0.f, 0.f, 0.f, 0.f);
            if (gr < NN) f = x4[(size_t)gr * 32 + c4];
            const __half2 h0 = __float22half2_rn(make_float2(f.x, f.y));
            const __half2 h1 = __float22half2_rn(make_float2(f.z, f.w));
            uint2 st;
            st.x = *(const uint32_t*)&h0;
            st.y = *(const uint32_t*)&h1;
            *(uint2*)&as[r][c4 * 4] = st;
        }
    }
    __syncthreads();

    const int g  = lane >> 2, tg = lane & 3;
    const int row = wr * 16 + g;
    const int nbase = wc * 32;

    float c00 = 0.f, c01 = 0.f, c02 = 0.f, c03 = 0.f;
    float c10 = 0.f, c11 = 0.f, c12 = 0.f, c13 = 0.f;
    float c20 = 0.f, c21 = 0.f, c22 = 0.f, c23 = 0.f;
    float c30 = 0.f, c31 = 0.f, c32 = 0.f, c33 = 0.f;

    #pragma unroll 2
    for (int kt = 0; kt < 8; kt++) {
        const int kb = kt * 16 + tg * 2;
        const uint32_t a0 = *(const uint32_t*)&as[row][kb];
        const uint32_t a1 = *(const uint32_t*)&as[row + 8][kb];
        const uint32_t a2 = *(const uint32_t*)&as[row][kb + 8];
        const uint32_t a3 = *(const uint32_t*)&as[row + 8][kb + 8];
        const __half* bp0 = g_w1t + (size_t)(nbase + g) * FIN + kb;
        const __half* bp1 = bp0 + 8 * FIN;
        const __half* bp2 = bp0 + 16 * FIN;
        const __half* bp3 = bp0 + 24 * FIN;
        const uint32_t b00 = *(const uint32_t*)bp0, b01 = *(const uint32_t*)(bp0 + 8);
        const uint32_t b10 = *(const uint32_t*)bp1, b11 = *(const uint32_t*)(bp1 + 8);
        const uint32_t b20 = *(const uint32_t*)bp2, b21 = *(const uint32_t*)(bp2 + 8);
        const uint32_t b30 = *(const uint32_t*)bp3, b31 = *(const uint32_t*)(bp3 + 8);
        MMA16816(c00, c01, c02, c03, a0, a1, a2, a3, b00, b01);
        MMA16816(c10, c11, c12, c13, a0, a1, a2, a3, b10, b11);
        MMA16816(c20, c21, c22, c23, a0, a1, a2, a3, b20, b21);
        MMA16816(c30, c31, c32, c33, a0, a1, a2, a3, b30, b31);
    }

    const int r0 = m0 + row;
    const int cb = nbase + tg * 2;
    *(__half2*)&g_h1h[(size_t)r0 * F1 + cb]            = __float22half2_rn(make_float2(c00, c01));
    *(__half2*)&g_h1h[(size_t)(r0 + 8) * F1 + cb]      = __float22half2_rn(make_float2(c02, c03));
    *(__half2*)&g_h1h[(size_t)r0 * F1 + cb + 8]        = __float22half2_rn(make_float2(c10, c11));
    *(__half2*)&g_h1h[(size_t)(r0 + 8) * F1 + cb + 8]  = __float22half2_rn(make_float2(c12, c13));
    *(__half2*)&g_h1h[(size_t)r0 * F1 + cb + 16]       = __float22half2_rn(make_float2(c20, c21));
    *(__half2*)&g_h1h[(size_t)(r0 + 8) * F1 + cb + 16] = __float22half2_rn(make_float2(c22, c23));
    *(__half2*)&g_h1h[(size_t)r0 * F1 + cb + 24]       = __float22half2_rn(make_float2(c30, c31));
    *(__half2*)&g_h1h[(size_t)(r0 + 8) * F1 + cb + 24] = __float22half2_rn(make_float2(c32, c33));

    // fused att1 dots: per (row, head=wc) quad-reduce across tg lanes
    const float av0 = as1[cb],      av1 = as1[cb + 1];
    const float av2 = as1[cb + 8],  av3 = as1[cb + 9];
    const float av4 = as1[cb + 16], av5 = as1[cb + 17];
    const float av6 = as1[cb + 24], av7 = as1[cb + 25];
    const float dv0 = ad1[cb],      dv1 = ad1[cb + 1];
    const float dv2 = ad1[cb + 8],  dv3 = ad1[cb + 9];
    const float dv4 = ad1[cb + 16], dv5 = ad1[cb + 17];
    const float dv6 = ad1[cb + 24], dv7 = ad1[cb + 25];

    float sA = c00*av0 + c01*av1 + c10*av2 + c11*av3 + c20*av4 + c21*av5 + c30*av6 + c31*av7;
    float dA = c00*dv0 + c01*dv1 + c10*dv2 + c11*dv3 + c20*dv4 + c21*dv5 + c30*dv6 + c31*dv7;
    float sB = c02*av0 + c03*av1 + c12*av2 + c13*av3 + c22*av4 + c23*av5 + c32*av6 + c33*av7;
    float dB = c02*dv0 + c03*dv1 + c12*dv2 + c13*dv3 + c22*dv4 + c23*dv5 + c32*dv6 + c33*dv7;
    #pragma unroll
    for (int o = 1; o < 4; o <<= 1) {
        sA += __shfl_xor_sync(FULL, sA, o);
        dA += __shfl_xor_sync(FULL, dA, o);
        sB += __shfl_xor_sync(FULL, sB, o);
        dB += __shfl_xor_sync(FULL, dB, o);
    }
    if (tg == 0) {
        if (r0 < NN)     { g_as1[r0 * HEADS + wc] = sA;       g_ad1[r0 * HEADS + wc] = dA; }
        if (r0 + 8 < NN) { g_as1[(r0 + 8) * HEADS + wc] = sB; g_ad1[(r0 + 8) * HEADS + wc] = dB; }
    }
}

// ---------------- TC GEMM 2 (+fused att2 dots via smem reduce) -----------
__global__ __launch_bounds__(512) void k_gemm2_tc(
        const float* __restrict__ as2, const float* __restrict__ ad2) {
    __shared__ __half as[64][136];
    __shared__ float reds[4][64];
    __shared__ float redd[4][64];
    const int m0  = blockIdx.x * 64;
    const int tid = threadIdx.x, lane = tid & 31, w = tid >> 5;
    const int wr  = w & 3, wc = w >> 2;

    {   // load A tile 64x128 fp16 = 1024 uint4: 512 threads x 2
        const uint4* srcA = (const uint4*)(g_x2h + (size_t)m0 * FIN);
        const int u0 = tid, u1 = tid + 512;
        const int r0_ = u0 >> 4, c0_ = (u0 & 15) << 3;
        const int r1_ = u1 >> 4, c1_ = (u1 & 15) << 3;
        *(uint4*)&as[r0_][c0_] = srcA[u0];
        *(uint4*)&as[r1_][c1_] = srcA[u1];
    }
    __syncthreads();

    const int g  = lane >> 2, tg = lane & 3;
    const int row = wr * 16 + g;
    const int nbase = wc * 8;

    float c00 = 0.f, c01 = 0.f, c02 = 0.f, c03 = 0.f;

    #pragma unroll 2
    for (int kt = 0; kt < 8; kt++) {
        const int kb = kt * 16 + tg * 2;
        const uint32_t a0 = *(const uint32_t*)&as[row][kb];
        const uint32_t a1 = *(const uint32_t*)&as[row + 8][kb];
        const uint32_t a2 = *(const uint32_t*)&as[row][kb + 8];
        const uint32_t a3 = *(const uint32_t*)&as[row + 8][kb + 8];
        const __half* bp0 = g_w2t + (size_t)(nbase + g) * FIN + kb;
        const uint32_t b00 = *(const uint32_t*)bp0, b01 = *(const uint32_t*)(bp0 + 8);
        MMA16816(c00, c01, c02, c03, a0, a1, a2, a3, b00, b01);
    }

    const int r0 = m0 + row;
    const int cb = nbase + tg * 2;
    *(__half2*)&g_h2h[(size_t)r0 * HID + cb]       = __float22half2_rn(make_float2(c00, c01));
    *(__half2*)&g_h2h[(size_t)(r0 + 8) * HID + cb] = __float22half2_rn(make_float2(c02, c03));

    // fused att2: quad-reduce within warp, cross-warp (wc) reduce via smem
    const float av0 = as2[cb], av1 = as2[cb + 1];
    const float dv0 = ad2[cb], dv1 = ad2[cb + 1];
    float sA = c00 * av0 + c01 * av1;
    float dA = c00 * dv0 + c01 * dv1;
    float sB = c02 * av0 + c03 * av1;
    float dB = c02 * dv0 + c03 * dv1;
    #pragma unroll
    for (int o = 1; o < 4; o <<= 1) {
        sA += __shfl_xor_sync(FULL, sA, o);
        dA += __shfl_xor_sync(FULL, dA, o);
        sB += __shfl_xor_sync(FULL, sB, o);
        dB += __shfl_xor_sync(FULL, dB, o);
    }
    if (tg == 0) {
        reds[wc][row]     = sA;  redd[wc][row]     = dA;
        reds[wc][row + 8] = sB;  redd[wc][row + 8] = dB;
    }
    __syncthreads();
    if (tid < 64) {
        const int n = m0 + tid;
        if (n < NN) {
            g_as2[n] = reds[0][tid] + reds[1][tid] + reds[2][tid] + reds[3][tid];
            g_ad2[n] = redd[0][tid] + redd[1][tid] + redd[2][tid] + redd[3][tid];
        }
    }
}

// ---------------- K_AGG1: gather layer 1, in-register edge weights -------
__global__ void k_agg1(const float* __restrict__ b1) {
    const int di   = blockIdx.x * 8 + (threadIdx.x >> 5);
    const int lane = threadIdx.x & 31;
    if (di >= NN) return;
    const int beg = g_rs[di], end = g_rs[di + 1];
    const int h8   = lane >> 3;
    const int hsel = lane & 3;
    const int esel = lane >> 2;
    const float adv = g_ad1[di * 4 + hsel];

    float ax = 0.f, ay = 0.f, az = 0.f, aw = 0.f, den = 0.f;

    for (int p0 = beg; p0 < end; p0 += 32) {
        const int m  = min(32, end - p0);
        const int sl = (p0 + lane < end) ? g_es[p0 + lane] : 0;
        const int nc = (m + 7) >> 3;
        for (int c = 0; c < nc; c++) {
            const int base = c * 8;
            const int  sle = __shfl_sync(FULL, sl, base + esel);
            float w = 0.f;
            if (p0 + base + esel < end)
                w = __expf(lrelu(__ldg(&g_as1[sle * 4 + hsel]) + adv));
            den += w;
            const int mm = m - base;
            if (mm >= 8) {
                #pragma unroll
                for (int j = 0; j < 8; j++) {
                    const int   si = __shfl_sync(FULL, sl, base + j);
                    const float wj = __shfl_sync(FULL, w, j * 4 + h8);
                    const uint2 u  = __ldg((const uint2*)&g_h1h[(size_t)si * F1 + lane * 4]);
                    const float2 f0 = __half22float2(*(const __half2*)&u.x);
                    const float2 f1 = __half22float2(*(const __half2*)&u.y);
                    ax += wj * f0.x; ay += wj * f0.y; az += wj * f1.x; aw += wj * f1.y;
                }
            } else {
                for (int j = 0; j < mm; j++) {
                    const int   si = __shfl_sync(FULL, sl, base + j);
                    const float wj = __shfl_sync(FULL, w, j * 4 + h8);
                    const uint2 u  = __ldg((const uint2*)&g_h1h[(size_t)si * F1 + lane * 4]);
                    const float2 f0 = __half22float2(*(const __half2*)&u.x);
                    const float2 f1 = __half22float2(*(const __half2*)&u.y);
                    ax += wj * f0.x; ay += wj * f0.y; az += wj * f1.x; aw += wj * f1.y;
                }
            }
        }
    }
    den += __shfl_xor_sync(FULL, den, 4);
    den += __shfl_xor_sync(FULL, den, 8);
    den += __shfl_xor_sync(FULL, den, 16);
    const float denF = __shfl_sync(FULL, den, h8);

    const float4 bb = *(const float4*)&b1[lane * 4];
    const float inv = 1.f / denF;
    const float ox = fmaxf(ax * inv + bb.x, 0.f);
    const float oy = fmaxf(ay * inv + bb.y, 0.f);
    const float oz = fmaxf(az * inv + bb.z, 0.f);
    const float ow = fmaxf(aw * inv + bb.w, 0.f);
    const __half2 p0 = __float22half2_rn(make_float2(ox, oy));
    const __half2 p1 = __float22half2_rn(make_float2(oz, ow));
    uint2 st;
    st.x = *(const uint32_t*)&p0;
    st.y = *(const uint32_t*)&p1;
    *(uint2*)&g_x2h[(size_t)di * F1 + lane * 4] = st;
}

// ---------------- K_AGG2: gather layer 2 (fused weights) + mean-pool -----
__global__ void k_agg2(const int* __restrict__ batch, const float* __restrict__ b2) {
    const int di   = blockIdx.x * 8 + (threadIdx.x >> 5);
    const int lane = threadIdx.x & 31;
    if (di >= NN) return;
    const int   beg = g_rs[di], end = g_rs[di + 1];
    const float ad  = g_ad2[di];

    float a0 = 0.f, a1 = 0.f, a2 = 0.f, a3 = 0.f, den = 0.f;
    for (int p0 = beg; p0 < end; p0 += 32) {
        const int  m     = min(32, end - p0);
        const bool valid = (p0 + lane < end);
        const int   sl = valid ? g_es[p0 + lane] : 0;
        const float wl = valid ? __expf(lrelu(__ldg(&g_as2[sl]) + ad)) : 0.f;
        int j = 0;
        for (; j + 4 <= m; j += 4) {
            const int   s0 = __shfl_sync(FULL, sl, j);
            const int   s1 = __shfl_sync(FULL, sl, j + 1);
            const int   s2 = __shfl_sync(FULL, sl, j + 2);
            const int   s3 = __shfl_sync(FULL, sl, j + 3);
            const float w0 = __shfl_sync(FULL, wl, j);
            const float w1 = __shfl_sync(FULL, wl, j + 1);
            const float w2 = __shfl_sync(FULL, wl, j + 2);
            const float w3 = __shfl_sync(FULL, wl, j + 3);
            a0 += w0 * __half2float(__ldg(&g_h2h[(size_t)s0 * HID + lane]));
            a1 += w1 * __half2float(__ldg(&g_h2h[(size_t)s1 * HID + lane]));
            a2 += w2 * __half2float(__ldg(&g_h2h[(size_t)s2 * HID + lane]));
            a3 += w3 * __half2float(__ldg(&g_h2h[(size_t)s3 * HID + lane]));
            den += (w0 + w1) + (w2 + w3);
        }
        for (; j < m; j++) {
            const int   s0 = __shfl_sync(FULL, sl, j);
            const float w0 = __shfl_sync(FULL, wl, j);
            a0 += w0 * __half2float(__ldg(&g_h2h[(size_t)s0 * HID + lane]));
            den += w0;
        }
    }
    const float acc = (a0 + a1) + (a2 + a3);
    const float v = fmaxf(acc / den + b2[lane], 0.f);
    const int g = batch[di];
    atomicAdd(&g_psum[g * HID + lane], v);
    if (lane == 0) atomicAdd(&g_cnt[g], 1.f);
}

// ---------------- K8: final FC + pooled-state cleanup --------------------
__global__ void k8_fc(const float* __restrict__ fcw, const float* __restrict__ fcb,
                      float* __restrict__ out) {
    const int tid = threadIdx.x;       // block = exactly GG*OUTD = 640 threads
    const int g = tid / OUTD, o = tid % OUTD;
    const float inv = 1.f / fmaxf(g_cnt[g], 1.f);
    float acc = fcb[o];
    #pragma unroll
    for (int c = 0; c < HID; c++)
        acc += g_psum[g * HID + c] * inv * fcw[c * OUTD + o];
    out[tid] = acc;
    __syncthreads();                   // all reads of psum/cnt done
    for (int i = tid; i < GG * HID; i += GG * OUTD) g_psum[i] = 0.f;
    if (tid < GG) g_cnt[tid] = 0.f;
}

// ---------------- launch ----------------
extern "C" void kernel_launch(void* const* d_in, const int* in_sizes, int n_in,
                              void* d_out, int out_size) {
    const float* x    = (const float*)d_in[0];
    const int*   esrc = (const int*)  d_in[1];
    const int*   edst = (const int*)  d_in[2];
    const int*   batch= (const int*)  d_in[3];
    const float* W1   = (const float*)d_in[4];
    const float* as1  = (const float*)d_in[5];
    const float* ad1  = (const float*)d_in[6];
    const float* b1   = (const float*)d_in[7];
    const float* W2   = (const float*)d_in[8];
    const float* as2  = (const float*)d_in[9];
    const float* ad2  = (const float*)d_in[10];
    const float* b2   = (const float*)d_in[11];
    const float* fcw  = (const float*)d_in[12];
    const float* fcb  = (const float*)d_in[13];
    float* out = (float*)d_out;

    // one-time host resources (not device memory; identical launch DAG every call)
    static cudaStream_t s_csr = nullptr, s_w = nullptr;
    static cudaEvent_t  ev_fork = nullptr, ev_join = nullptr, ev_w = nullptr;
    if (s_csr == nullptr) {
        cudaStreamCreateWithFlags(&s_csr, cudaStreamNonBlocking);
        cudaStreamCreateWithFlags(&s_w,   cudaStreamNonBlocking);
        cudaEventCreateWithFlags(&ev_fork, cudaEventDisableTiming);
        cudaEventCreateWithFlags(&ev_join, cudaEventDisableTiming);
        cudaEventCreateWithFlags(&ev_w,    cudaEventDisableTiming);
    }

    // 3-way fork: CSR chain on s_csr; weight cvt on s_w; x-GEMM on default
    cudaEventRecord(ev_fork, 0);
    cudaStreamWaitEvent(s_csr, ev_fork, 0);
    cudaStreamWaitEvent(s_w,   ev_fork, 0);

    k_count  <<<(EE + 255) / 256, 256, 0, s_csr>>>(edst);
    k_scan   <<<NB, 256, 0, s_csr>>>();
    k_scatter<<<(ET / 2 + 255) / 256, 256, 0, s_csr>>>(esrc, edst);
    cudaEventRecord(ev_join, s_csr);

    k_cvtw<<<64, 256, 0, s_w>>>(W1, W2);
    cudaEventRecord(ev_w, s_w);

    cudaStreamWaitEvent(0, ev_w, 0);        // gemm1 needs w1t
    k_gemm1_tc<<<NNP / 64, 512>>>(x, as1, ad1);

    cudaStreamWaitEvent(0, ev_join, 0);     // aggregation needs CSR
    k_agg1    <<<(NN + 7) / 8, 256>>>(b1);
    k_gemm2_tc<<<NNP / 64, 512>>>(as2, ad2);
    k_agg2    <<<(NN + 7) / 8, 256>>>(batch, b2);
    k8_fc     <<<1, 640>>>(fcw, fcb, out);
}